// round 12
// baseline (speedup 1.0000x reference)
#include <cuda_runtime.h>
#include <stdint.h>

#define B_   128
#define S_   512
#define T_   24
#define D_   256
#define H_   4
#define HD_  64
#define N_   (B_*S_)            // 65536
#define NT_  (N_*T_)            // 1572864
#define KOSC (-500.0f)
// noise cutoff: |dn|<=0.165, skip when exp(-500 I^2) < 6e-6  <=>  I^2 > 0.0241
#define NOISE_TH 0.0241f

typedef unsigned long long ull;
typedef unsigned short ushortx;

// Precomputed tables (device globals: no allocation allowed)
__device__ __align__(16) float d_k [H_*T_*HD_];
__device__ __align__(16) float d_v [H_*T_*HD_];
__device__ __align__(16) float d_qt[H_*T_*HD_];
__device__ __align__(16) float d_qu[H_*B_*HD_];
__device__ __align__(16) float d_st[H_*T_*T_];
__device__ __align__(16) float d_su[H_*B_*T_];
__device__ __align__(16) float d_W [96*280];   // [kt][c]: c<256 unify, c>=256 head
__device__ __align__(16) float d_bias[280];
__device__ unsigned d_ku[2];
__device__ unsigned d_kv[2];

// ---------- packed f32x2 helpers ----------
__device__ __forceinline__ void ffma2(ull &d, ull a, ull b) {
    asm("fma.rn.f32x2 %0, %1, %2, %0;" : "+l"(d) : "l"(a), "l"(b));
}
__device__ __forceinline__ ull addf2(ull a, ull b) {
    ull r; asm("add.rn.f32x2 %0, %1, %2;" : "=l"(r) : "l"(a), "l"(b)); return r;
}

// ---------- JAX threefry2x32 (exact) ----------
__device__ __forceinline__ void tf2x32(unsigned k0, unsigned k1,
                                       unsigned x0, unsigned x1,
                                       unsigned &o0, unsigned &o1) {
    unsigned k2 = k0 ^ k1 ^ 0x1BD11BDAu;
    x0 += k0; x1 += k1;
#define RD_(r) { x0 += x1; x1 = (x1 << (r)) | (x1 >> (32 - (r))); x1 ^= x0; }
    RD_(13) RD_(15) RD_(26) RD_(6)   x0 += k1; x1 += k2 + 1u;
    RD_(17) RD_(29) RD_(16) RD_(24)  x0 += k2; x1 += k0 + 2u;
    RD_(13) RD_(15) RD_(26) RD_(6)   x0 += k0; x1 += k1 + 3u;
    RD_(17) RD_(29) RD_(16) RD_(24)  x0 += k1; x1 += k2 + 4u;
    RD_(13) RD_(15) RD_(26) RD_(6)   x0 += k2; x1 += k0 + 5u;
#undef RD_
    o0 = x0; o1 = x1;
}

// XLA ErfInv32 (Giles) with fast log: w = -log(1-x^2), 1-x^2 single-rounded
__device__ __forceinline__ float erfinv_fast(float x) {
    float w = -__logf(fmaf(-x, x, 1.0f));
    float p;
    if (w < 5.0f) {
        w = w - 2.5f;
        p =              2.81022636e-08f;
        p = fmaf(p, w,   3.43273939e-07f);
        p = fmaf(p, w,  -3.5233877e-06f);
        p = fmaf(p, w,  -4.39150654e-06f);
        p = fmaf(p, w,   0.00021858087f);
        p = fmaf(p, w,  -0.00125372503f);
        p = fmaf(p, w,  -0.00417768164f);
        p = fmaf(p, w,   0.246640727f);
        p = fmaf(p, w,   1.50140941f);
    } else {
        w = sqrtf(w) - 3.0f;
        p =             -0.000200214257f;
        p = fmaf(p, w,   0.000100950558f);
        p = fmaf(p, w,   0.00134934322f);
        p = fmaf(p, w,  -0.00367342844f);
        p = fmaf(p, w,   0.00573950773f);
        p = fmaf(p, w,  -0.0076224613f);
        p = fmaf(p, w,   0.00943887047f);
        p = fmaf(p, w,   1.00167406f);
        p = fmaf(p, w,   2.83297682f);
    }
    return p * x;
}

__device__ __forceinline__ float bits_to_noise(unsigned bits) {
    const float LO = -0.99999994039535522461f;
    float u01 = __uint_as_float((bits >> 9) | 0x3f800000u) - 1.0f;
    float val = fmaxf(LO, u01 * 2.0f + LO);
    return 1.41421356237f * erfinv_fast(val) * 0.01f;
}

// ---------- Precompute 1: 96 ktv blocks + 128 qu blocks (4 users each) ----------
__global__ __launch_bounds__(512) void kpre1(
        const float* __restrict__ ts, const float* __restrict__ sts,
        const int* __restrict__ user, const float* __restrict__ upref,
        const float* __restrict__ wq_w, const float* __restrict__ wq_b,
        const float* __restrict__ wk_w, const float* __restrict__ wk_b,
        const float* __restrict__ wv_w, const float* __restrict__ wv_b) {
    __shared__ float redbuf[2048];
    int unit = blockIdx.x;
    int e = threadIdx.x & 63, part = threadIdx.x >> 6;
    int d0 = part * 32;
    if (blockIdx.x == 0 && threadIdx.x == 0) {
        unsigned a0, a1, b0, b1;
        tf2x32(0u, 42u, 0u, 0u, a0, a1);
        tf2x32(0u, 42u, 0u, 1u, b0, b1);
        d_ku[0] = a0; d_ku[1] = a1; d_kv[0] = b0; d_kv[1] = b1;
    }
    if (unit < 96) {
        float (*red)[8][64] = (float(*)[8][64])redbuf;
        int h = unit / 24, t = unit % 24;
        const float* xs = sts + t * D_ + d0;
        const float* xt = ts  + t * D_ + d0;
        const float* wk = wk_w + (h*D_ + d0)*HD_ + e;
        const float* wv = wv_w + (h*D_ + d0)*HD_ + e;
        const float* wq = wq_w + (h*2*D_ + D_ + d0)*HD_ + e;
        float k0=0,k1=0,k2=0,k3=0, v0=0,v1=0,v2=0,v3=0, q0=0,q1=0,q2=0,q3=0;
        #pragma unroll
        for (int d = 0; d < 32; d += 4) {
            float x0 = xs[d], x1 = xs[d+1], x2 = xs[d+2], x3 = xs[d+3];
            k0 = fmaf(x0, wk[(d  )*HD_], k0); k1 = fmaf(x1, wk[(d+1)*HD_], k1);
            k2 = fmaf(x2, wk[(d+2)*HD_], k2); k3 = fmaf(x3, wk[(d+3)*HD_], k3);
            v0 = fmaf(x0, wv[(d  )*HD_], v0); v1 = fmaf(x1, wv[(d+1)*HD_], v1);
            v2 = fmaf(x2, wv[(d+2)*HD_], v2); v3 = fmaf(x3, wv[(d+3)*HD_], v3);
            float y0 = xt[d], y1 = xt[d+1], y2 = xt[d+2], y3 = xt[d+3];
            q0 = fmaf(y0, wq[(d  )*HD_], q0); q1 = fmaf(y1, wq[(d+1)*HD_], q1);
            q2 = fmaf(y2, wq[(d+2)*HD_], q2); q3 = fmaf(y3, wq[(d+3)*HD_], q3);
        }
        red[0][part][e] = (k0 + k1) + (k2 + k3);
        red[1][part][e] = (v0 + v1) + (v2 + v3);
        red[2][part][e] = (q0 + q1) + (q2 + q3);
        __syncthreads();
        if (part < 3) {
            float s = ((red[part][0][e] + red[part][1][e])
                     + (red[part][2][e] + red[part][3][e]))
                    + ((red[part][4][e] + red[part][5][e])
                     + (red[part][6][e] + red[part][7][e]));
            if      (part == 0) d_k [unit*HD_ + e] = s + wk_b[h*HD_ + e];
            else if (part == 1) d_v [unit*HD_ + e] = s + wv_b[h*HD_ + e];
            else                d_qt[unit*HD_ + e] = s;
        }
    } else {
        float (*red)[64][4] = (float(*)[64][4])redbuf;
        int j = unit - 96;                 // 0..127
        int h = j >> 5;                    // 0..3
        int bg = (j & 31) * 4;             // base user row
        const float* up0 = upref + (size_t)user[bg+0]*D_ + d0;
        const float* up1 = upref + (size_t)user[bg+1]*D_ + d0;
        const float* up2 = upref + (size_t)user[bg+2]*D_ + d0;
        const float* up3 = upref + (size_t)user[bg+3]*D_ + d0;
        const float* wq = wq_w + (h*2*D_ + d0)*HD_ + e;
        float a0=0, a1=0, a2=0, a3=0;
        #pragma unroll 8
        for (int d = 0; d < 32; d++) {
            float w = wq[d*HD_];
            a0 = fmaf(__ldg(up0 + d), w, a0);
            a1 = fmaf(__ldg(up1 + d), w, a1);
            a2 = fmaf(__ldg(up2 + d), w, a2);
            a3 = fmaf(__ldg(up3 + d), w, a3);
        }
        red[part][e][0] = a0; red[part][e][1] = a1;
        red[part][e][2] = a2; red[part][e][3] = a3;
        __syncthreads();
        if (part < 4) {
            float s = ((red[0][e][part] + red[1][e][part])
                     + (red[2][e][part] + red[3][e][part]))
                    + ((red[4][e][part] + red[5][e][part])
                     + (red[6][e][part] + red[7][e][part]));
            d_qu[(h*B_ + bg + part)*HD_ + e] = s + wq_b[h*HD_ + e];
        }
    }
}

// ---------- Precompute 2: W, st, su, biases.  grid = 144, block = 256 ----------
__global__ __launch_bounds__(256) void kpre2(
        const float* __restrict__ uw, const float* __restrict__ ub,
        const float* __restrict__ hw, const float* __restrict__ hb) {
    int bid = blockIdx.x, tid = threadIdx.x;
    if (bid < 96) {
        int h = bid / 24, t = bid % 24, kt = bid;
        {
            float a0 = 0, a1 = 0, a2 = 0, a3 = 0;
            const float* u = uw + h*HD_*D_ + tid;
            #pragma unroll 4
            for (int e = 0; e < HD_; e += 4) {
                a0 = fmaf(d_v[kt*HD_+e  ], u[(e  )*D_], a0);
                a1 = fmaf(d_v[kt*HD_+e+1], u[(e+1)*D_], a1);
                a2 = fmaf(d_v[kt*HD_+e+2], u[(e+2)*D_], a2);
                a3 = fmaf(d_v[kt*HD_+e+3], u[(e+3)*D_], a3);
            }
            d_W[kt*280 + tid] = (a0 + a1) + (a2 + a3);
        }
        if (tid < 24) {
            float a0 = 0, a1 = 0;
            const float* hwp = hw + h*HD_*T_ + tid;
            #pragma unroll 4
            for (int e = 0; e < HD_; e += 2) {
                a0 = fmaf(d_v[kt*HD_+e  ], hwp[(e  )*T_], a0);
                a1 = fmaf(d_v[kt*HD_+e+1], hwp[(e+1)*T_], a1);
            }
            d_W[kt*280 + 256 + tid] = a0 + a1;
        }
        if (tid >= 32 && tid < 56) {
            int t2 = tid - 32;
            float a0 = 0, a1 = 0;
            #pragma unroll 4
            for (int e = 0; e < HD_; e += 2) {
                a0 = fmaf(d_qt[kt*HD_+e  ], d_k[(h*T_+t2)*HD_+e  ], a0);
                a1 = fmaf(d_qt[kt*HD_+e+1], d_k[(h*T_+t2)*HD_+e+1], a1);
            }
            d_st[(h*T_ + t)*T_ + t2] = (a0 + a1) * 0.125f;
        }
        if (bid == 0) d_bias[tid] = ub[tid];
        if (bid == 1 && tid < 24) d_bias[256 + tid] = hb[tid];
    } else {
        int j = (bid - 96) * 256 + tid;
        int hb2 = j / 24, t = j % 24;
        int h = hb2 >> 7;
        float a0 = 0, a1 = 0, a2 = 0, a3 = 0;
        #pragma unroll 4
        for (int e = 0; e < HD_; e += 4) {
            a0 = fmaf(d_qu[hb2*HD_+e  ], d_k[(h*T_+t)*HD_+e  ], a0);
            a1 = fmaf(d_qu[hb2*HD_+e+1], d_k[(h*T_+t)*HD_+e+1], a1);
            a2 = fmaf(d_qu[hb2*HD_+e+2], d_k[(h*T_+t)*HD_+e+2], a2);
            a3 = fmaf(d_qu[hb2*HD_+e+3], d_k[(h*T_+t)*HD_+e+3], a3);
        }
        d_su[hb2*T_ + t] = ((a0 + a1) + (a2 + a3)) * 0.125f;
    }
}

// ---------- Main fused kernel ----------
#define TR_    128
#define KS_    98                       // ull stride of shPd rows
#define ZS_    98                       // float stride of shZ rows
#define SHPD_B (TR_*KS_*8)              // 100352 bytes
#define QOFF_B 51200                    // queue byte offset (above shZ's 50176)
#define SHWH_O SHPD_B                   // head-W ull[96][12] after shPd
#define SMEM_BYTES (SHPD_B + 96*12*8)   // 109568

__global__ __launch_bounds__(512, 2) void kmain(const int* __restrict__ hour,
                                                const int* __restrict__ mask,
                                                float* __restrict__ out) {
    extern __shared__ char smembuf[];
    ull*   shPd = (ull*)smembuf;                       // probs, duplicated pairs
    float* shZ  = (float*)smembuf;                     // z overlay [128][98]
    ushortx* queue = (ushortx*)(smembuf + QOFF_B);     // <=12288 entries
    ull*   shWh = (ull*)(smembuf + SHWH_O);            // head W pairs [96][12]
    __shared__ int cnt;

    int tid = threadIdx.x;
    int lane = tid & 31;
    int tile0 = blockIdx.x * TR_;
    if (tid == 0) cnt = 0;
    // head-W copy: shWh[kk][c] = (W[kk][256+2c], W[kk][256+2c+1])
    for (int i = tid; i < 96*12; i += 512) {
        int kk = i / 12, c = i - kk*12;
        shWh[i] = *(const ull*)(d_W + kk*280 + 256 + 2*c);
    }
    __syncthreads();

    unsigned ku0 = d_ku[0], ku1 = d_ku[1];
    unsigned kv0 = d_kv[0], kv1 = d_kv[1];

    // ---- Stage A1: z = relu(I); need test on I^2 (no exp); warp-scan compact ----
    {
        int r = tid >> 2, h = tid & 3;
        int n = tile0 + r;
        int b = n >> 9;
        int tau = hour[n];
        const int4*   mp  = (const int4*)(mask + n*24);
        const float4* sup = (const float4*)(d_su + (h*B_ + b)*T_);
        const float4* stp = (const float4*)(d_st + (h*T_ + tau)*T_);
        float* zrow = shZ + r*ZS_ + h*24;
        unsigned needmask = 0u;
        #pragma unroll
        for (int j = 0; j < 6; j++) {
            int4 m4 = __ldg(mp + j);
            float4 s4 = sup[j];
            float4 t4 = stp[j];
            int   mv[4] = {m4.x, m4.y, m4.z, m4.w};
            float sv[4] = {s4.x, s4.y, s4.z, s4.w};
            float tv[4] = {t4.x, t4.y, t4.z, t4.w};
            #pragma unroll
            for (int q = 0; q < 4; q++) {
                int t = j*4 + q;
                float z = 0.0f;
                if (!mv[q]) {
                    float I = sv[q] + tv[q];
                    z = fmaxf(I, 0.0f);
                    if (I*I < NOISE_TH) needmask |= (1u << t);
                }
                zrow[t] = z;
            }
        }
        // warp-scan compaction
        int cc = __popc(needmask);
        int pre = cc;
        #pragma unroll
        for (int off = 1; off < 32; off <<= 1) {
            int v = __shfl_up_sync(0xffffffffu, pre, off);
            if (lane >= off) pre += v;
        }
        int wtotal = __shfl_sync(0xffffffffu, pre, 31);
        int base = 0;
        if (lane == 31 && wtotal) base = atomicAdd(&cnt, wtotal);
        base = __shfl_sync(0xffffffffu, base, 31);
        int wpos = base + pre - cc;
        unsigned m = needmask;
        while (m) {
            int t = __ffs(m) - 1;
            m &= m - 1u;
            queue[wpos++] = (ushortx)(tid*24 + t);
        }
    }
    __syncthreads();

    // ---- Stage A2: dense threefry over queued slots ----
    {
        int total = cnt;
        for (int i = tid; i < total; i += 512) {
            int sid = queue[i];
            int t = sid % 24;
            int rh = sid / 24;
            int r = rh >> 2, h = rh & 3;
            int n = tile0 + r;
            int b = n >> 9;
            int tau = hour[n];
            float I = d_su[(h*B_ + b)*T_ + t] + d_st[(h*T_ + tau)*T_ + t];
            float g = __expf((KOSC * I) * I);
            unsigned idx = (unsigned)(n*24 + t) + (unsigned)h * (unsigned)NT_;
            unsigned a0, a1, c0, c1;
            tf2x32(ku0, ku1, 0u, idx, a0, a1);
            tf2x32(kv0, kv1, 0u, idx, c0, c1);
            float dn = bits_to_noise(a0 ^ a1) - bits_to_noise(c0 ^ c1);
            shZ[r*ZS_ + h*24 + t] += dn * g;
        }
    }
    __syncthreads();

    // ---- Stage B: softmax in regs; sync; write duplicated pairs ----
    float pp[24];
    {
        int r = tid >> 2, h = tid & 3;
        const float* zrow = shZ + r*ZS_ + h*24;
        #pragma unroll
        for (int t = 0; t < 24; t++) pp[t] = zrow[t];
        float mx = pp[0];
        #pragma unroll
        for (int t = 1; t < 24; t++) mx = fmaxf(mx, pp[t]);
        float s = 0.0f;
        #pragma unroll
        for (int t = 0; t < 24; t++) { pp[t] = __expf(pp[t] - mx); s += pp[t]; }
        float inv = __fdividef(1.0f, s);
        #pragma unroll
        for (int t = 0; t < 24; t++) pp[t] *= inv;
    }
    __syncthreads();   // all z reads done before prob writes overwrite region
    {
        int r = tid >> 2, h = tid & 3;
        float2* dst = (float2*)(shPd + (size_t)r * KS_ + h*24);
        #pragma unroll
        for (int t = 0; t < 24; t++) dst[t] = make_float2(pp[t], pp[t]);
    }
    __syncthreads();

    // ---- Head phase: 24 logit cols; (p,p) pairs x headW col-pairs ----
    {
        int r = tid >> 2, q = tid & 3;
        const ull* prow = shPd + (size_t)r * KS_;
        ull a0 = 0ull, a1 = 0ull, a2 = 0ull;
        #pragma unroll 4
        for (int kk = 0; kk < 96; kk++) {
            ull p2 = prow[kk];
            ffma2(a0, p2, shWh[kk*12 + q*3 + 0]);
            ffma2(a1, p2, shWh[kk*12 + q*3 + 1]);
            ffma2(a2, p2, shWh[kk*12 + q*3 + 2]);
        }
        int n = tile0 + r;
        float* outlg = out + (size_t)N_ * D_ + (size_t)n * T_;
        int cp = q*3;
        float2 f0 = *(float2*)&a0, f1 = *(float2*)&a1, f2 = *(float2*)&a2;
        f0.x += d_bias[256 + 2*cp + 0]; f0.y += d_bias[256 + 2*cp + 1];
        f1.x += d_bias[256 + 2*cp + 2]; f1.y += d_bias[256 + 2*cp + 3];
        f2.x += d_bias[256 + 2*cp + 4]; f2.y += d_bias[256 + 2*cp + 5];
        *(float2*)(outlg + 2*cp + 0) = f0;
        *(float2*)(outlg + 2*cp + 2) = f1;
        *(float2*)(outlg + 2*cp + 4) = f2;
    }

    // ---- Main GEMM: probs[128,96] @ W[96,256] ----
    // 4 passes of (4 rows x 4 cols) per thread: 16-reg accumulators, no spill.
    #pragma unroll
    for (int pass = 0; pass < 4; pass++) {
        int u = tid + pass * 512;
        int rg = u >> 6, cs = u & 63;      // 32 rowgroups x 64 colsets
        int r0 = rg * 4, c0 = cs * 4;
        ull acc0[4], acc1[4];
        #pragma unroll
        for (int i = 0; i < 4; i++) { acc0[i] = 0ull; acc1[i] = 0ull; }
        const float* wbase = d_W + c0;
        #pragma unroll 4
        for (int kk = 0; kk < 96; kk += 2) {
            uint4 wa = __ldg((const uint4*)(wbase + kk*280));
            uint4 wb = __ldg((const uint4*)(wbase + (kk+1)*280));
            ull wax = ((const ulonglong2*)&wa)->x;
            ull way = ((const ulonglong2*)&wa)->y;
            ull wbx = ((const ulonglong2*)&wb)->x;
            ull wby = ((const ulonglong2*)&wb)->y;
            #pragma unroll
            for (int i = 0; i < 4; i++) {
                ulonglong2 pr = *(const ulonglong2*)(shPd + (size_t)(r0+i)*KS_ + kk);
                ffma2(acc0[i], pr.x, wax);
                ffma2(acc1[i], pr.x, way);
                ffma2(acc0[i], pr.y, wbx);
                ffma2(acc1[i], pr.y, wby);
            }
        }
        uint4 bi4 = __ldg((const uint4*)(d_bias + c0));
        ull bix = ((const ulonglong2*)&bi4)->x;
        ull biy = ((const ulonglong2*)&bi4)->y;
        #pragma unroll
        for (int i = 0; i < 4; i++) {
            int n = tile0 + r0 + i;
            ulonglong2 o;
            o.x = addf2(acc0[i], bix);
            o.y = addf2(acc1[i], biy);
            *(ulonglong2*)(out + (size_t)n*D_ + c0) = o;
        }
    }
}

extern "C" void kernel_launch(void* const* d_in, const int* in_sizes, int n_in,
                              void* d_out, int out_size) {
    const float* ts    = (const float*)d_in[0];
    const float* sts   = (const float*)d_in[1];
    const int*   user  = (const int*)d_in[3];
    const int*   hour  = (const int*)d_in[4];
    const int*   mask  = (const int*)d_in[5];
    const float* upref = (const float*)d_in[6];
    const float* wq_w  = (const float*)d_in[7];
    const float* wq_b  = (const float*)d_in[8];
    const float* wk_w  = (const float*)d_in[9];
    const float* wk_b  = (const float*)d_in[10];
    const float* wv_w  = (const float*)d_in[11];
    const float* wv_b  = (const float*)d_in[12];
    const float* uw    = (const float*)d_in[13];
    const float* ub    = (const float*)d_in[14];
    const float* hw    = (const float*)d_in[15];
    const float* hb    = (const float*)d_in[16];
    float* out = (float*)d_out;

    cudaFuncSetAttribute(kmain, cudaFuncAttributeMaxDynamicSharedMemorySize,
                         (int)SMEM_BYTES);

    kpre1<<<224, 512>>>(ts, sts, user, upref, wq_w, wq_b, wk_w, wk_b, wv_w, wv_b);
    kpre2<<<144, 256>>>(uw, ub, hw, hb);
    kmain<<<N_ / TR_, 512, SMEM_BYTES>>>(hour, mask, out);
}

// round 14
// speedup vs baseline: 1.1744x; 1.1744x over previous
#include <cuda_runtime.h>
#include <stdint.h>

#define B_   128
#define S_   512
#define T_   24
#define D_   256
#define H_   4
#define HD_  64
#define N_   (B_*S_)            // 65536
#define NT_  (N_*T_)            // 1572864
#define KOSC (-500.0f)
#define NOISE_TH 0.0241f

typedef unsigned long long ull;
typedef unsigned short ushortx;

__device__ __align__(16) float d_k [H_*T_*HD_];
__device__ __align__(16) float d_v [H_*T_*HD_];
__device__ __align__(16) float d_qt[H_*T_*HD_];
__device__ __align__(16) float d_qu[H_*B_*HD_];
__device__ __align__(16) float d_st[H_*T_*T_];
__device__ __align__(16) float d_su[H_*B_*T_];
__device__ __align__(16) float d_W [96*280];   // [kt][c]: c<256 unify, c>=256 head
__device__ __align__(16) float d_bias[280];
__device__ unsigned d_ku[2];
__device__ unsigned d_kv[2];

// ---------- packed f32x2 helpers ----------
__device__ __forceinline__ void ffma2(ull &d, ull a, ull b) {
    asm("fma.rn.f32x2 %0, %1, %2, %0;" : "+l"(d) : "l"(a), "l"(b));
}
__device__ __forceinline__ ull addf2(ull a, ull b) {
    ull r; asm("add.rn.f32x2 %0, %1, %2;" : "=l"(r) : "l"(a), "l"(b)); return r;
}
__device__ __forceinline__ ull dup2(float v) {
    unsigned b = __float_as_uint(v);
    ull r; asm("mov.b64 %0, {%1, %1};" : "=l"(r) : "r"(b)); return r;
}

// ---------- JAX threefry2x32 (exact) ----------
__device__ __forceinline__ void tf2x32(unsigned k0, unsigned k1,
                                       unsigned x0, unsigned x1,
                                       unsigned &o0, unsigned &o1) {
    unsigned k2 = k0 ^ k1 ^ 0x1BD11BDAu;
    x0 += k0; x1 += k1;
#define RD_(r) { x0 += x1; x1 = (x1 << (r)) | (x1 >> (32 - (r))); x1 ^= x0; }
    RD_(13) RD_(15) RD_(26) RD_(6)   x0 += k1; x1 += k2 + 1u;
    RD_(17) RD_(29) RD_(16) RD_(24)  x0 += k2; x1 += k0 + 2u;
    RD_(13) RD_(15) RD_(26) RD_(6)   x0 += k0; x1 += k1 + 3u;
    RD_(17) RD_(29) RD_(16) RD_(24)  x0 += k1; x1 += k2 + 4u;
    RD_(13) RD_(15) RD_(26) RD_(6)   x0 += k2; x1 += k0 + 5u;
#undef RD_
    o0 = x0; o1 = x1;
}

__device__ __forceinline__ float erfinv_fast(float x) {
    float w = -__logf(fmaf(-x, x, 1.0f));
    float p;
    if (w < 5.0f) {
        w = w - 2.5f;
        p =              2.81022636e-08f;
        p = fmaf(p, w,   3.43273939e-07f);
        p = fmaf(p, w,  -3.5233877e-06f);
        p = fmaf(p, w,  -4.39150654e-06f);
        p = fmaf(p, w,   0.00021858087f);
        p = fmaf(p, w,  -0.00125372503f);
        p = fmaf(p, w,  -0.00417768164f);
        p = fmaf(p, w,   0.246640727f);
        p = fmaf(p, w,   1.50140941f);
    } else {
        w = sqrtf(w) - 3.0f;
        p =             -0.000200214257f;
        p = fmaf(p, w,   0.000100950558f);
        p = fmaf(p, w,   0.00134934322f);
        p = fmaf(p, w,  -0.00367342844f);
        p = fmaf(p, w,   0.00573950773f);
        p = fmaf(p, w,  -0.0076224613f);
        p = fmaf(p, w,   0.00943887047f);
        p = fmaf(p, w,   1.00167406f);
        p = fmaf(p, w,   2.83297682f);
    }
    return p * x;
}

__device__ __forceinline__ float bits_to_noise(unsigned bits) {
    const float LO = -0.99999994039535522461f;
    float u01 = __uint_as_float((bits >> 9) | 0x3f800000u) - 1.0f;
    float val = fmaxf(LO, u01 * 2.0f + LO);
    return 1.41421356237f * erfinv_fast(val) * 0.01f;
}

// ---------- Precompute 1 (unchanged from R11) ----------
__global__ __launch_bounds__(512) void kpre1(
        const float* __restrict__ ts, const float* __restrict__ sts,
        const int* __restrict__ user, const float* __restrict__ upref,
        const float* __restrict__ wq_w, const float* __restrict__ wq_b,
        const float* __restrict__ wk_w, const float* __restrict__ wk_b,
        const float* __restrict__ wv_w, const float* __restrict__ wv_b) {
    __shared__ float redbuf[2048];
    int unit = blockIdx.x;
    int e = threadIdx.x & 63, part = threadIdx.x >> 6;
    int d0 = part * 32;
    if (blockIdx.x == 0 && threadIdx.x == 0) {
        unsigned a0, a1, b0, b1;
        tf2x32(0u, 42u, 0u, 0u, a0, a1);
        tf2x32(0u, 42u, 0u, 1u, b0, b1);
        d_ku[0] = a0; d_ku[1] = a1; d_kv[0] = b0; d_kv[1] = b1;
    }
    if (unit < 96) {
        float (*red)[8][64] = (float(*)[8][64])redbuf;
        int h = unit / 24, t = unit % 24;
        const float* xs = sts + t * D_ + d0;
        const float* xt = ts  + t * D_ + d0;
        const float* wk = wk_w + (h*D_ + d0)*HD_ + e;
        const float* wv = wv_w + (h*D_ + d0)*HD_ + e;
        const float* wq = wq_w + (h*2*D_ + D_ + d0)*HD_ + e;
        float k0=0,k1=0,k2=0,k3=0, v0=0,v1=0,v2=0,v3=0, q0=0,q1=0,q2=0,q3=0;
        #pragma unroll
        for (int d = 0; d < 32; d += 4) {
            float x0 = xs[d], x1 = xs[d+1], x2 = xs[d+2], x3 = xs[d+3];
            k0 = fmaf(x0, wk[(d  )*HD_], k0); k1 = fmaf(x1, wk[(d+1)*HD_], k1);
            k2 = fmaf(x2, wk[(d+2)*HD_], k2); k3 = fmaf(x3, wk[(d+3)*HD_], k3);
            v0 = fmaf(x0, wv[(d  )*HD_], v0); v1 = fmaf(x1, wv[(d+1)*HD_], v1);
            v2 = fmaf(x2, wv[(d+2)*HD_], v2); v3 = fmaf(x3, wv[(d+3)*HD_], v3);
            float y0 = xt[d], y1 = xt[d+1], y2 = xt[d+2], y3 = xt[d+3];
            q0 = fmaf(y0, wq[(d  )*HD_], q0); q1 = fmaf(y1, wq[(d+1)*HD_], q1);
            q2 = fmaf(y2, wq[(d+2)*HD_], q2); q3 = fmaf(y3, wq[(d+3)*HD_], q3);
        }
        red[0][part][e] = (k0 + k1) + (k2 + k3);
        red[1][part][e] = (v0 + v1) + (v2 + v3);
        red[2][part][e] = (q0 + q1) + (q2 + q3);
        __syncthreads();
        if (part < 3) {
            float s = ((red[part][0][e] + red[part][1][e])
                     + (red[part][2][e] + red[part][3][e]))
                    + ((red[part][4][e] + red[part][5][e])
                     + (red[part][6][e] + red[part][7][e]));
            if      (part == 0) d_k [unit*HD_ + e] = s + wk_b[h*HD_ + e];
            else if (part == 1) d_v [unit*HD_ + e] = s + wv_b[h*HD_ + e];
            else                d_qt[unit*HD_ + e] = s;
        }
    } else {
        float (*red)[64][4] = (float(*)[64][4])redbuf;
        int j = unit - 96;
        int h = j >> 5;
        int bg = (j & 31) * 4;
        const float* up0 = upref + (size_t)user[bg+0]*D_ + d0;
        const float* up1 = upref + (size_t)user[bg+1]*D_ + d0;
        const float* up2 = upref + (size_t)user[bg+2]*D_ + d0;
        const float* up3 = upref + (size_t)user[bg+3]*D_ + d0;
        const float* wq = wq_w + (h*2*D_ + d0)*HD_ + e;
        float a0=0, a1=0, a2=0, a3=0;
        #pragma unroll 8
        for (int d = 0; d < 32; d++) {
            float w = wq[d*HD_];
            a0 = fmaf(__ldg(up0 + d), w, a0);
            a1 = fmaf(__ldg(up1 + d), w, a1);
            a2 = fmaf(__ldg(up2 + d), w, a2);
            a3 = fmaf(__ldg(up3 + d), w, a3);
        }
        red[part][e][0] = a0; red[part][e][1] = a1;
        red[part][e][2] = a2; red[part][e][3] = a3;
        __syncthreads();
        if (part < 4) {
            float s = ((red[0][e][part] + red[1][e][part])
                     + (red[2][e][part] + red[3][e][part]))
                    + ((red[4][e][part] + red[5][e][part])
                     + (red[6][e][part] + red[7][e][part]));
            d_qu[(h*B_ + bg + part)*HD_ + e] = s + wq_b[h*HD_ + e];
        }
    }
}

// ---------- Precompute 2 (unchanged) ----------
__global__ __launch_bounds__(256) void kpre2(
        const float* __restrict__ uw, const float* __restrict__ ub,
        const float* __restrict__ hw, const float* __restrict__ hb) {
    int bid = blockIdx.x, tid = threadIdx.x;
    if (bid < 96) {
        int h = bid / 24, t = bid % 24, kt = bid;
        {
            float a0 = 0, a1 = 0, a2 = 0, a3 = 0;
            const float* u = uw + h*HD_*D_ + tid;
            #pragma unroll 4
            for (int e = 0; e < HD_; e += 4) {
                a0 = fmaf(d_v[kt*HD_+e  ], u[(e  )*D_], a0);
                a1 = fmaf(d_v[kt*HD_+e+1], u[(e+1)*D_], a1);
                a2 = fmaf(d_v[kt*HD_+e+2], u[(e+2)*D_], a2);
                a3 = fmaf(d_v[kt*HD_+e+3], u[(e+3)*D_], a3);
            }
            d_W[kt*280 + tid] = (a0 + a1) + (a2 + a3);
        }
        if (tid < 24) {
            float a0 = 0, a1 = 0;
            const float* hwp = hw + h*HD_*T_ + tid;
            #pragma unroll 4
            for (int e = 0; e < HD_; e += 2) {
                a0 = fmaf(d_v[kt*HD_+e  ], hwp[(e  )*T_], a0);
                a1 = fmaf(d_v[kt*HD_+e+1], hwp[(e+1)*T_], a1);
            }
            d_W[kt*280 + 256 + tid] = a0 + a1;
        }
        if (tid >= 32 && tid < 56) {
            int t2 = tid - 32;
            float a0 = 0, a1 = 0;
            #pragma unroll 4
            for (int e = 0; e < HD_; e += 2) {
                a0 = fmaf(d_qt[kt*HD_+e  ], d_k[(h*T_+t2)*HD_+e  ], a0);
                a1 = fmaf(d_qt[kt*HD_+e+1], d_k[(h*T_+t2)*HD_+e+1], a1);
            }
            d_st[(h*T_ + t)*T_ + t2] = (a0 + a1) * 0.125f;
        }
        if (bid == 0) d_bias[tid] = ub[tid];
        if (bid == 1 && tid < 24) d_bias[256 + tid] = hb[tid];
    } else {
        int j = (bid - 96) * 256 + tid;
        int hb2 = j / 24, t = j % 24;
        int h = hb2 >> 7;
        float a0 = 0, a1 = 0, a2 = 0, a3 = 0;
        #pragma unroll 4
        for (int e = 0; e < HD_; e += 4) {
            a0 = fmaf(d_qu[hb2*HD_+e  ], d_k[(h*T_+t)*HD_+e  ], a0);
            a1 = fmaf(d_qu[hb2*HD_+e+1], d_k[(h*T_+t)*HD_+e+1], a1);
            a2 = fmaf(d_qu[hb2*HD_+e+2], d_k[(h*T_+t)*HD_+e+2], a2);
            a3 = fmaf(d_qu[hb2*HD_+e+3], d_k[(h*T_+t)*HD_+e+3], a3);
        }
        d_su[hb2*T_ + t] = ((a0 + a1) + (a2 + a3)) * 0.125f;
    }
}

// ---------- Main fused kernel ----------
#define TR_    128
#define ZS_    98                         // float stride of probs/z rows
#define SHP_B  (TR_*ZS_*4)                // 50176 bytes (z, then probs in place)
#define QOFF_B SHP_B                      // queue overlays W-tile region (A-phase only)
#define WB0_B  SHP_B                      // W tile buf0 (GEMM phase only)
#define WTS_   264                        // W tile float stride
#define WTB_   (16*WTS_*4)                // 16896 bytes per tile buffer
#define WB1_B  (WB0_B + WTB_)
#define SHWH_B (WB1_B + WTB_)             // 83968: head-W ull[96][12]
#define SMEM_BYTES (SHWH_B + 96*12*8)     // 93184

__global__ __launch_bounds__(512, 2) void kmain(const int* __restrict__ hour,
                                                const int* __restrict__ mask,
                                                float* __restrict__ out) {
    extern __shared__ char smembuf[];
    float* shP  = (float*)smembuf;                     // z / probs [128][98]
    ushortx* queue = (ushortx*)(smembuf + QOFF_B);     // <=12288 entries
    ull*   shWh = (ull*)(smembuf + SHWH_B);            // head W pairs [96][12]
    __shared__ int cnt;

    int tid = threadIdx.x;
    int lane = tid & 31;
    int tile0 = blockIdx.x * TR_;
    if (tid == 0) cnt = 0;
    for (int i = tid; i < 96*12; i += 512) {
        int kk = i / 12, c = i - kk*12;
        shWh[i] = *(const ull*)(d_W + kk*280 + 256 + 2*c);
    }
    __syncthreads();

    unsigned ku0 = d_ku[0], ku1 = d_ku[1];
    unsigned kv0 = d_kv[0], kv1 = d_kv[1];

    // ---- Stage A1: z = relu(I); need test on I^2; warp-scan compaction ----
    {
        int r = tid >> 2, h = tid & 3;
        int n = tile0 + r;
        int b = n >> 9;
        int tau = hour[n];
        const int4*   mp  = (const int4*)(mask + n*24);
        const float4* sup = (const float4*)(d_su + (h*B_ + b)*T_);
        const float4* stp = (const float4*)(d_st + (h*T_ + tau)*T_);
        float* zrow = shP + r*ZS_ + h*24;
        unsigned needmask = 0u;
        #pragma unroll
        for (int j = 0; j < 6; j++) {
            int4 m4 = __ldg(mp + j);
            float4 s4 = sup[j];
            float4 t4 = stp[j];
            int   mv[4] = {m4.x, m4.y, m4.z, m4.w};
            float sv[4] = {s4.x, s4.y, s4.z, s4.w};
            float tv[4] = {t4.x, t4.y, t4.z, t4.w};
            #pragma unroll
            for (int q = 0; q < 4; q++) {
                int t = j*4 + q;
                float z = 0.0f;
                if (!mv[q]) {
                    float I = sv[q] + tv[q];
                    z = fmaxf(I, 0.0f);
                    if (I*I < NOISE_TH) needmask |= (1u << t);
                }
                zrow[t] = z;
            }
        }
        int cc = __popc(needmask);
        int pre = cc;
        #pragma unroll
        for (int off = 1; off < 32; off <<= 1) {
            int v = __shfl_up_sync(0xffffffffu, pre, off);
            if (lane >= off) pre += v;
        }
        int wtotal = __shfl_sync(0xffffffffu, pre, 31);
        int base = 0;
        if (lane == 31 && wtotal) base = atomicAdd(&cnt, wtotal);
        base = __shfl_sync(0xffffffffu, base, 31);
        int wpos = base + pre - cc;
        unsigned m = needmask;
        while (m) {
            int t = __ffs(m) - 1;
            m &= m - 1u;
            queue[wpos++] = (ushortx)(tid*24 + t);
        }
    }
    __syncthreads();

    // ---- Stage A2: dense threefry over queued slots ----
    {
        int total = cnt;
        for (int i = tid; i < total; i += 512) {
            int sid = queue[i];
            int t = sid % 24;
            int rh = sid / 24;
            int r = rh >> 2, h = rh & 3;
            int n = tile0 + r;
            int b = n >> 9;
            int tau = hour[n];
            float I = d_su[(h*B_ + b)*T_ + t] + d_st[(h*T_ + tau)*T_ + t];
            float g = __expf((KOSC * I) * I);
            unsigned idx = (unsigned)(n*24 + t) + (unsigned)h * (unsigned)NT_;
            unsigned a0, a1, c0, c1;
            tf2x32(ku0, ku1, 0u, idx, a0, a1);
            tf2x32(kv0, kv1, 0u, idx, c0, c1);
            float dn = bits_to_noise(a0 ^ a1) - bits_to_noise(c0 ^ c1);
            shP[r*ZS_ + h*24 + t] += dn * g;
        }
    }
    __syncthreads();

    // ---- Stage B: softmax in regs, write probs IN PLACE (own row: no hazard) ----
    {
        int r = tid >> 2, h = tid & 3;
        float* zrow = shP + r*ZS_ + h*24;
        float pp[24];
        #pragma unroll
        for (int t = 0; t < 24; t++) pp[t] = zrow[t];
        float mx = pp[0];
        #pragma unroll
        for (int t = 1; t < 24; t++) mx = fmaxf(mx, pp[t]);
        float s = 0.0f;
        #pragma unroll
        for (int t = 0; t < 24; t++) { pp[t] = __expf(pp[t] - mx); s += pp[t]; }
        float inv = __fdividef(1.0f, s);
        #pragma unroll
        for (int t = 0; t < 24; t++) zrow[t] = pp[t] * inv;
    }
    __syncthreads();

    // ---- Head phase: 24 logit cols; scalar prob + dup mov + col-pair FFMA2 ----
    {
        int r = tid >> 2, q = tid & 3;
        const float* prow = shP + r*ZS_;
        ull a0 = 0ull, a1 = 0ull, a2 = 0ull;
        #pragma unroll 4
        for (int kk = 0; kk < 96; kk++) {
            ull p2 = dup2(prow[kk]);
            ffma2(a0, p2, shWh[kk*12 + q*3 + 0]);
            ffma2(a1, p2, shWh[kk*12 + q*3 + 1]);
            ffma2(a2, p2, shWh[kk*12 + q*3 + 2]);
        }
        int n = tile0 + r;
        float* outlg = out + (size_t)N_ * D_ + (size_t)n * T_;
        int cp = q*3;
        float2 f0 = *(float2*)&a0, f1 = *(float2*)&a1, f2 = *(float2*)&a2;
        f0.x += d_bias[256 + 2*cp + 0]; f0.y += d_bias[256 + 2*cp + 1];
        f1.x += d_bias[256 + 2*cp + 2]; f1.y += d_bias[256 + 2*cp + 3];
        f2.x += d_bias[256 + 2*cp + 4]; f2.y += d_bias[256 + 2*cp + 5];
        *(float2*)(outlg + 2*cp + 0) = f0;
        *(float2*)(outlg + 2*cp + 2) = f1;
        *(float2*)(outlg + 2*cp + 4) = f2;
    }
    __syncthreads();   // probs fully read by head? (GEMM also reads; queue region now free)

    // ---- Main GEMM: probs[128,96] @ W[96,256]; W k-tiles via smem, dbl-buffered ----
    {
        int ldrow = tid >> 5;                 // cooperative-load row (0..15)
        int ldc   = ((2*tid) & 63) * 4;       // 2 float4 = 32B contiguous per thread
        #pragma unroll 1
        for (int pass = 0; pass < 2; pass++) {
            int r0 = ((tid >> 6) + pass*8) * 8;    // 0..56 / 64..120
            int c0 = (tid & 63) * 4;
            ull acc0[8], acc1[8];
            #pragma unroll
            for (int i = 0; i < 8; i++) { acc0[i] = 0ull; acc1[i] = 0ull; }
            // load tile 0 -> buf0
            {
                float4* dst = (float4*)(smembuf + WB0_B + (ldrow*WTS_ + ldc)*4);
                const float4* src = (const float4*)(d_W + ldrow*280 + ldc);
                dst[0] = src[0]; dst[1] = src[1];
            }
            __syncthreads();
            #pragma unroll
            for (int t = 0; t < 6; t++) {
                if (t > 0) __syncthreads();       // STS of tile t visible
                float4 pf0, pf1;
                if (t < 5) {
                    const float4* src =
                        (const float4*)(d_W + ((t+1)*16 + ldrow)*280 + ldc);
                    pf0 = src[0]; pf1 = src[1];
                }
                const float* wb = (const float*)(smembuf + ((t & 1) ? WB1_B : WB0_B));
                #pragma unroll
                for (int kl = 0; kl < 16; kl += 2) {
                    int kk = t*16 + kl;
                    ulonglong2 wa = *(const ulonglong2*)(wb + kl*WTS_ + c0);
                    ulonglong2 wbv = *(const ulonglong2*)(wb + (kl+1)*WTS_ + c0);
                    #pragma unroll
                    for (int i = 0; i < 8; i++) {
                        float2 pr = *(const float2*)(shP + (r0+i)*ZS_ + kk);
                        ull pA = dup2(pr.x);
                        ull pB = dup2(pr.y);
                        ffma2(acc0[i], pA, wa.x);
                        ffma2(acc1[i], pA, wa.y);
                        ffma2(acc0[i], pB, wbv.x);
                        ffma2(acc1[i], pB, wbv.y);
                    }
                }
                if (t < 5) {
                    float4* dst = (float4*)(smembuf + ((t & 1) ? WB0_B : WB1_B)
                                            + (ldrow*WTS_ + ldc)*4);
                    dst[0] = pf0; dst[1] = pf1;
                }
            }
            uint4 bi4 = __ldg((const uint4*)(d_bias + c0));
            ull bix = ((const ulonglong2*)&bi4)->x;
            ull biy = ((const ulonglong2*)&bi4)->y;
            #pragma unroll
            for (int i = 0; i < 8; i++) {
                int n = tile0 + r0 + i;
                ulonglong2 o;
                o.x = addf2(acc0[i], bix);
                o.y = addf2(acc1[i], biy);
                *(ulonglong2*)(out + (size_t)n*D_ + c0) = o;
            }
            if (pass == 0) __syncthreads();   // buf reuse across passes
        }
    }
}

extern "C" void kernel_launch(void* const* d_in, const int* in_sizes, int n_in,
                              void* d_out, int out_size) {
    const float* ts    = (const float*)d_in[0];
    const float* sts   = (const float*)d_in[1];
    const int*   user  = (const int*)d_in[3];
    const int*   hour  = (const int*)d_in[4];
    const int*   mask  = (const int*)d_in[5];
    const float* upref = (const float*)d_in[6];
    const float* wq_w  = (const float*)d_in[7];
    const float* wq_b  = (const float*)d_in[8];
    const float* wk_w  = (const float*)d_in[9];
    const float* wk_b  = (const float*)d_in[10];
    const float* wv_w  = (const float*)d_in[11];
    const float* wv_b  = (const float*)d_in[12];
    const float* uw    = (const float*)d_in[13];
    const float* ub    = (const float*)d_in[14];
    const float* hw    = (const float*)d_in[15];
    const float* hb    = (const float*)d_in[16];
    float* out = (float*)d_out;

    cudaFuncSetAttribute(kmain, cudaFuncAttributeMaxDynamicSharedMemorySize,
                         (int)SMEM_BYTES);

    kpre1<<<224, 512>>>(ts, sts, user, upref, wq_w, wq_b, wk_w, wk_b, wv_w, wv_b);
    kpre2<<<144, 256>>>(uw, ub, hw, hb);
    kmain<<<N_ / TR_, 512, SMEM_BYTES>>>(hour, mask, out);
}